// round 8
// baseline (speedup 1.0000x reference)
#include <cuda_runtime.h>
#include <cuda_bf16.h>
#include <cstdint>

// ---------------- problem constants ----------------
#define NB      32
#define NNODE   4096
#define NEDGE   16384
#define F1      16
#define F2      128
#define F3      256
#define KHEAD   (NNODE * F3)   // 1,048,576
#define NROWS   (NB * NNODE)   // 131072

// ---------------- scratch ----------------
__device__ float g_a1[(size_t)NB * NNODE * F1];
__device__ float g_h1[(size_t)NB * NNODE * F2];
__device__ float g_a2[(size_t)NB * NNODE * F2];
__device__ float g_deg[NNODE];
__device__ float g_dinv[NNODE];
__device__ int   g_cnt[NNODE];
__device__ int   g_fill[NNODE];
__device__ int   g_rowptr[NNODE + 1];
__device__ int   g_col[NEDGE];
__device__ float g_nrm[NEDGE];
__device__ float g_P[NB * 80];
__device__ int   g_is64;
__device__ float g_Pp2[2048][16 * 80];   // 10.5 MB per-block head partials (16 batches x 80)

// ---------------- helpers ----------------
// truncation-based split of a float pair into bf16x2 hi/lo words.
__device__ __forceinline__ void split2(float x, float y, uint32_t& hi, uint32_t& lo) {
    uint32_t xb = __float_as_uint(x), yb = __float_as_uint(y);
    hi = __byte_perm(xb, yb, 0x7632);
    float lx = x - __uint_as_float(xb & 0xffff0000u);
    float ly = y - __uint_as_float(yb & 0xffff0000u);
    lo = __byte_perm(__float_as_uint(lx), __float_as_uint(ly), 0x7632);
}
// D += A(16x16 bf16) * B(16x8 bf16), f32 accum. m16n8k16 fragments.
__device__ __forceinline__ void mma_bf16(float* d, const uint32_t* a, uint32_t b0, uint32_t b1) {
    asm volatile(
        "mma.sync.aligned.m16n8k16.row.col.f32.bf16.bf16.f32 "
        "{%0,%1,%2,%3}, {%4,%5,%6,%7}, {%8,%9}, {%0,%1,%2,%3};"
        : "+f"(d[0]), "+f"(d[1]), "+f"(d[2]), "+f"(d[3])
        : "r"(a[0]), "r"(a[1]), "r"(a[2]), "r"(a[3]), "r"(b0), "r"(b1));
}
// head weight fragment load: rows r0, r0+1, r0+8, r0+9 at output-col ncol of [v1W|advW|0]
__device__ __forceinline__ void load_w4(float* dst, const float* __restrict__ v1W,
                                        const float* __restrict__ advW, int r0, int ncol) {
    if (ncol < 64) {
        const float* p = v1W + (size_t)r0 * 64 + ncol;
        dst[0] = p[0]; dst[1] = p[64]; dst[2] = p[512]; dst[3] = p[576];
    } else if (ncol < 76) {
        const float* p = advW + (size_t)r0 * 12 + (ncol - 64);
        dst[0] = p[0]; dst[1] = p[12]; dst[2] = p[96]; dst[3] = p[108];
    } else {
        dst[0] = dst[1] = dst[2] = dst[3] = 0.f;
    }
}

// ---------------- edge read helper ----------------
__device__ __forceinline__ void read_edge(const void* ei, int e, int& src, int& dst) {
    if (g_is64) {
        const long long* p = (const long long*)ei;
        src = (int)p[e]; dst = (int)p[NEDGE + e];
    } else {
        const int* p = (const int*)ei;
        src = p[e]; dst = p[NEDGE + e];
    }
}

// ---------------- K0 ----------------
__global__ void zero_kernel(const int* __restrict__ ei32) {
    int i = blockIdx.x * blockDim.x + threadIdx.x;
    if (i < NNODE) { g_deg[i] = 0.f; g_cnt[i] = 0; g_fill[i] = 0; }
    if (i == 0) {
        int any = 0;
        for (int k = 0; k < 256; k++) any |= ei32[2 * k + 1];
        g_is64 = (any == 0) ? 1 : 0;
    }
}

// ---------------- K1 ----------------
__global__ void degcnt_kernel(const void* __restrict__ ei, const float* __restrict__ ew) {
    int e = blockIdx.x * blockDim.x + threadIdx.x;
    if (e >= NEDGE) return;
    int src, dst;
    read_edge(ei, e, src, dst);
    atomicAdd(&g_deg[dst], ew[e]);
    atomicAdd(&g_cnt[dst], 1);
}

// ---------------- K2 ----------------
__global__ __launch_bounds__(1024) void scan_kernel() {
    __shared__ int ss[1024];
    int t = threadIdx.x;
    int loc[4]; int s = 0;
#pragma unroll
    for (int i = 0; i < 4; i++) { loc[i] = s; s += g_cnt[4 * t + i]; }
    ss[t] = s;
    __syncthreads();
    int mysum = s;
    for (int off = 1; off < 1024; off <<= 1) {
        int v = (t >= off) ? ss[t - off] : 0;
        __syncthreads();
        ss[t] += v;
        __syncthreads();
    }
    int excl = ss[t] - mysum;
#pragma unroll
    for (int i = 0; i < 4; i++) {
        g_rowptr[4 * t + i] = excl + loc[i];
        g_dinv[4 * t + i] = rsqrtf(g_deg[4 * t + i] + 1.0f);
    }
    if (t == 1023) g_rowptr[NNODE] = ss[t];
}

// ---------------- K3 ----------------
__global__ void fill_kernel(const void* __restrict__ ei, const float* __restrict__ ew) {
    int e = blockIdx.x * blockDim.x + threadIdx.x;
    if (e >= NEDGE) return;
    int src, dst;
    read_edge(ei, e, src, dst);
    int pos = g_rowptr[dst] + atomicAdd(&g_fill[dst], 1);
    g_col[pos] = src;
    g_nrm[pos] = ew[e] * g_dinv[src] * g_dinv[dst];
}

// ---------------- K4: aggregate x (F=16) ----------------
__global__ __launch_bounds__(512) void agg16_kernel(const float* __restrict__ x) {
    int n = blockIdx.x;
    int tid = threadIdx.x;
    int b = tid >> 4, f = tid & 15;
    int beg = g_rowptr[n], end = g_rowptr[n + 1];
    float d = g_dinv[n];
    float d2 = d * d;
    const float* xb = x + (size_t)b * (NNODE * F1);
    float acc = d2 * xb[n * F1 + f];
    for (int j = beg; j < end; j++)
        acc = fmaf(g_nrm[j], xb[(size_t)g_col[j] * F1 + f], acc);
    g_a1[((size_t)b * NNODE + n) * F1 + f] = acc;
}

// ---------------- K5: gemm1 ----------------
__global__ __launch_bounds__(256) void gemm1_kernel(const float* __restrict__ W1, const float* __restrict__ b1) {
    __shared__ float Ws[16][128];
    __shared__ float bs[128];
    int tid = threadIdx.x;
    for (int id = tid; id < 16 * 128; id += 256) Ws[id >> 7][id & 127] = W1[id];
    if (tid < 128) bs[tid] = b1[tid];
    __syncthreads();
    int wid = tid >> 5, lane = tid & 31;
    size_t row = (size_t)blockIdx.x * 8 + wid;
    float av = (lane < 16) ? g_a1[row * F1 + lane] : 0.f;
    float acc[4] = {0.f, 0.f, 0.f, 0.f};
#pragma unroll
    for (int k = 0; k < 16; k++) {
        float a = __shfl_sync(0xffffffffu, av, k);
#pragma unroll
        for (int c = 0; c < 4; c++) acc[c] = fmaf(a, Ws[k][lane + 32 * c], acc[c]);
    }
#pragma unroll
    for (int c = 0; c < 4; c++)
        g_h1[row * F2 + lane + 32 * c] = fmaxf(acc[c] + bs[lane + 32 * c], 0.f);
}

// ---------------- K6: aggregate h1 (F=128) ----------------
__global__ __launch_bounds__(512) void agg128_kernel() {
    int n = blockIdx.x;
    int tid = threadIdx.x;
    int b = tid >> 4, q = tid & 15;
    int beg = g_rowptr[n], end = g_rowptr[n + 1];
    float d = g_dinv[n];
    float d2 = d * d;
    const float4* hb = (const float4*)g_h1 + (size_t)b * (NNODE * 32);
    float4 s0 = hb[(size_t)n * 32 + q];
    float4 s1 = hb[(size_t)n * 32 + 16 + q];
    float4 a0 = make_float4(d2 * s0.x, d2 * s0.y, d2 * s0.z, d2 * s0.w);
    float4 a1 = make_float4(d2 * s1.x, d2 * s1.y, d2 * s1.z, d2 * s1.w);
    for (int j = beg; j < end; j++) {
        float w = g_nrm[j];
        size_t c = (size_t)g_col[j] * 32;
        float4 v0 = hb[c + q];
        float4 v1 = hb[c + 16 + q];
        a0.x = fmaf(w, v0.x, a0.x); a0.y = fmaf(w, v0.y, a0.y);
        a0.z = fmaf(w, v0.z, a0.z); a0.w = fmaf(w, v0.w, a0.w);
        a1.x = fmaf(w, v1.x, a1.x); a1.y = fmaf(w, v1.y, a1.y);
        a1.z = fmaf(w, v1.z, a1.z); a1.w = fmaf(w, v1.w, a1.w);
    }
    float4* ob = (float4*)g_a2 + (size_t)b * (NNODE * 32);
    ob[(size_t)n * 32 + q] = a0;
    ob[(size_t)n * 32 + 16 + q] = a1;
}

// ---------------- K7: FUSED gemm2 + head ----------------
// Tile: 128 m-rows = 8 nodes x 16 batches, 128 cols (one half of F3).
// Grid: x = col half (2), y = node_tile*2 + batch_group (1024).
//   -> the 4 blocks sharing a node_tile's weight rows are launch-adjacent (L2 reuse).
// Stage 1: h2 tile = relu(a2 @ W2 + b2), bf16-split mma (as round 7), kept in SMEM f32.
// Stage 2: per-warp node: P[b][j] += sum_{col} h2[b,node,col] * W[node*256+colbase+col][j]
//   via m16n8k16 (M2 = 16 batches), weights direct-to-fragment with ring prefetch.
// SMEM: stage-1 staging (40 KB u32) then reused as o-tile f32 [128][132] (67.5 KB).
#define FG_P2    132
#define FG_SMEM  (128 * FG_P2 * 4)   // 67584

__global__ __launch_bounds__(256, 2) void gcn2head_kernel(const float* __restrict__ W2,
                                                          const float* __restrict__ b2,
                                                          const float* __restrict__ v1W,
                                                          const float* __restrict__ advW) {
    extern __shared__ float smf[];
    uint32_t* smu = (uint32_t*)smf;
    uint32_t* uAh = smu;            // [128][20]
    uint32_t* uAl = smu + 2560;
    uint32_t* uBh = smu + 5120;     // [128][20] (n-major)
    uint32_t* uBl = smu + 7680;

    int tid = threadIdx.x;
    int wid = tid >> 5, lane = tid & 31;
    int gid = lane >> 2, tig = lane & 3;
    int wm = wid & 1, wn = wid >> 1;
    int bx = blockIdx.x;            // col half
    int ntile = blockIdx.y >> 1;    // node tile (8 nodes)
    int bg = blockIdx.y & 1;        // batch group (16 batches)
    int n0 = bx * 128;
    int node0 = ntile * 8;

    // tile row r (0..127) = node_local*16 + batch_local  ->  g_a2 row
    // grow(r) = (bg*16 + (r&15))*NNODE + node0 + (r>>4)

    float acc[4][4][4];
#pragma unroll
    for (int i = 0; i < 4; i++)
#pragma unroll
        for (int j = 0; j < 4; j++)
#pragma unroll
            for (int r = 0; r < 4; r++) acc[i][j][r] = 0.f;

    float2 rA[8];
    float  rBx[8], rBy[8];
    // prefetch chunk 0
#pragma unroll
    for (int i = 0; i < 8; i++) {
        int idx = tid + i * 256;
        int m = idx >> 4, kp = idx & 15;
        size_t grow = (size_t)(bg * 16 + (m & 15)) * NNODE + node0 + (m >> 4);
        rA[i] = *(const float2*)(g_a2 + grow * F2 + 2 * kp);
    }
#pragma unroll
    for (int i = 0; i < 8; i++) {
        int idx = tid + i * 256;
        int kp = idx >> 7, n = idx & 127;
        rBx[i] = W2[(size_t)(2 * kp) * F3 + n0 + n];
        rBy[i] = W2[(size_t)(2 * kp + 1) * F3 + n0 + n];
    }

    for (int c = 0; c < 4; c++) {
        // stage current chunk
#pragma unroll
        for (int i = 0; i < 8; i++) {
            int idx = tid + i * 256;
            int m = idx >> 4, kp = idx & 15;
            uint32_t hi, lo;
            split2(rA[i].x, rA[i].y, hi, lo);
            uAh[m * 20 + kp] = hi;
            uAl[m * 20 + kp] = lo;
        }
#pragma unroll
        for (int i = 0; i < 8; i++) {
            int idx = tid + i * 256;
            int kp = idx >> 7, n = idx & 127;
            uint32_t hi, lo;
            split2(rBx[i], rBy[i], hi, lo);
            uBh[n * 20 + kp] = hi;
            uBl[n * 20 + kp] = lo;
        }
        __syncthreads();
        // prefetch next chunk
        if (c < 3) {
            int k0n = (c + 1) * 32;
#pragma unroll
            for (int i = 0; i < 8; i++) {
                int idx = tid + i * 256;
                int m = idx >> 4, kp = idx & 15;
                size_t grow = (size_t)(bg * 16 + (m & 15)) * NNODE + node0 + (m >> 4);
                rA[i] = *(const float2*)(g_a2 + grow * F2 + k0n + 2 * kp);
            }
#pragma unroll
            for (int i = 0; i < 8; i++) {
                int idx = tid + i * 256;
                int kp = idx >> 7, n = idx & 127;
                rBx[i] = W2[(size_t)(k0n + 2 * kp) * F3 + n0 + n];
                rBy[i] = W2[(size_t)(k0n + 2 * kp + 1) * F3 + n0 + n];
            }
        }
        // mma phase
#pragma unroll
        for (int ks = 0; ks < 2; ks++) {
            int kb = ks * 8;
#pragma unroll
            for (int mt = 0; mt < 4; mt++) {
                int r = wm * 64 + mt * 16 + gid;
                uint32_t ah[4], al[4];
                ah[0] = uAh[r * 20 + kb + tig];
                ah[1] = uAh[(r + 8) * 20 + kb + tig];
                ah[2] = uAh[r * 20 + kb + tig + 4];
                ah[3] = uAh[(r + 8) * 20 + kb + tig + 4];
                al[0] = uAl[r * 20 + kb + tig];
                al[1] = uAl[(r + 8) * 20 + kb + tig];
                al[2] = uAl[r * 20 + kb + tig + 4];
                al[3] = uAl[(r + 8) * 20 + kb + tig + 4];
#pragma unroll
                for (int nt = 0; nt < 4; nt++) {
                    int ncol = wn * 32 + nt * 8 + gid;
                    uint32_t bh0 = uBh[ncol * 20 + kb + tig];
                    uint32_t bh1 = uBh[ncol * 20 + kb + tig + 4];
                    uint32_t bl0 = uBl[ncol * 20 + kb + tig];
                    uint32_t bl1 = uBl[ncol * 20 + kb + tig + 4];
                    mma_bf16(acc[mt][nt], ah, bh0, bh1);
                    mma_bf16(acc[mt][nt], al, bh0, bh1);
                    mma_bf16(acc[mt][nt], ah, bl0, bl1);
                }
            }
        }
        __syncthreads();
    }

    // ---- stage-1 epilogue: bias + relu -> SMEM o-tile [128][FG_P2] (f32) ----
#pragma unroll
    for (int mt = 0; mt < 4; mt++) {
        int r = wm * 64 + mt * 16 + gid;
#pragma unroll
        for (int nt = 0; nt < 4; nt++) {
            int ccol = wn * 32 + nt * 8 + tig * 2;
            float bb0 = __ldg(b2 + n0 + ccol), bb1 = __ldg(b2 + n0 + ccol + 1);
            *(float2*)(smf + r * FG_P2 + ccol) =
                make_float2(fmaxf(acc[mt][nt][0] + bb0, 0.f),
                            fmaxf(acc[mt][nt][1] + bb1, 0.f));
            *(float2*)(smf + (r + 8) * FG_P2 + ccol) =
                make_float2(fmaxf(acc[mt][nt][2] + bb0, 0.f),
                            fmaxf(acc[mt][nt][3] + bb1, 0.f));
        }
    }

    // ---- stage 2: head. warp = node (wid), M2 = 16 batches, k2 = 128 cols ----
    int wrow_base = (node0 + wid) * 256 + n0;   // W row for col 0 of this warp's node
    float acc2[10][4];
#pragma unroll
    for (int j = 0; j < 10; j++)
#pragma unroll
        for (int r = 0; r < 4; r++) acc2[j][r] = 0.f;

    float wbuf[2][4];
    load_w4(wbuf[0], v1W, advW, wrow_base + 2 * tig, gid);   // (kstep 0, nt 0)
    __syncthreads();    // o-tile visible

#pragma unroll 1
    for (int kstep = 0; kstep < 8; kstep++) {
        int cs = kstep * 16 + 2 * tig;
        int base0 = (wid * 16 + gid) * FG_P2;
        int base1 = (wid * 16 + gid + 8) * FG_P2;
        float2 a0 = *(float2*)(smf + base0 + cs);
        float2 a1 = *(float2*)(smf + base1 + cs);
        float2 a2v = *(float2*)(smf + base0 + cs + 8);
        float2 a3v = *(float2*)(smf + base1 + cs + 8);
        uint32_t ah2[4], al2[4];
        split2(a0.x, a0.y, ah2[0], al2[0]);
        split2(a1.x, a1.y, ah2[1], al2[1]);
        split2(a2v.x, a2v.y, ah2[2], al2[2]);
        split2(a3v.x, a3v.y, ah2[3], al2[3]);
#pragma unroll
        for (int nt = 0; nt < 10; nt++) {
            int it = kstep * 10 + nt;
            int cur = it & 1, nxt = cur ^ 1;
            if (it < 79) {
                int itn = it + 1;
                int ksn = itn / 10, ntn = itn - ksn * 10;
                load_w4(wbuf[nxt], v1W, advW, wrow_base + ksn * 16 + 2 * tig, ntn * 8 + gid);
            }
            uint32_t bh0, bl0, bh1, bl1;
            split2(wbuf[cur][0], wbuf[cur][1], bh0, bl0);
            split2(wbuf[cur][2], wbuf[cur][3], bh1, bl1);
            mma_bf16(acc2[nt], ah2, bh0, bh1);
            mma_bf16(acc2[nt], al2, bh0, bh1);
            mma_bf16(acc2[nt], ah2, bl0, bl1);
        }
    }

    // ---- cross-warp reduce (8 node-warps) -> g_Pp2[block][16*80] ----
    __syncthreads();                 // o-tile dead; reuse as dump[8][1280]
    float* dump = smf + wid * 1280;
#pragma unroll
    for (int nt = 0; nt < 10; nt++) {
        int j = nt * 8 + tig * 2;
        dump[gid * 80 + j]           = acc2[nt][0];
        dump[gid * 80 + j + 1]       = acc2[nt][1];
        dump[(gid + 8) * 80 + j]     = acc2[nt][2];
        dump[(gid + 8) * 80 + j + 1] = acc2[nt][3];
    }
    __syncthreads();
    int blk = blockIdx.y * 2 + blockIdx.x;
    for (int i = tid; i < 1280; i += 256) {
        float s0 = smf[i]            + smf[1280 + i];
        float s1 = smf[2 * 1280 + i] + smf[3 * 1280 + i];
        float s2 = smf[4 * 1280 + i] + smf[5 * 1280 + i];
        float s3 = smf[6 * 1280 + i] + smf[7 * 1280 + i];
        g_Pp2[blk][i] = (s0 + s1) + (s2 + s3);
    }
}

// ---------------- K8: fold partials into g_P ----------------
// P[b][j] = sum over ntile(512) x bx(2) of g_Pp2[ntile*4 + (b>>4)*2 + bx][(b&15)*80 + j]
__global__ __launch_bounds__(256) void reduceP_kernel() {
    int i = blockIdx.x * 256 + threadIdx.x;   // 10 blocks x 256 = 2560
    if (i >= NB * 80) return;
    int b = i / 80, j = i - b * 80;
    int off = (b & 15) * 80 + j;
    int bg2 = (b >> 4) * 2;
    float s0 = 0.f, s1 = 0.f;
    for (int nt = 0; nt < 512; nt++) {
        s0 += g_Pp2[nt * 4 + bg2][off];
        s1 += g_Pp2[nt * 4 + bg2 + 1][off];
    }
    g_P[i] = s0 + s1;
}

// ---------------- K9: finish heads ----------------
__global__ __launch_bounds__(256) void final_kernel(const float* __restrict__ advb, const float* __restrict__ v1b,
                             const float* __restrict__ v2W, const float* __restrict__ v2b,
                             const float* __restrict__ v3W, const float* __restrict__ v3b,
                             float* __restrict__ out) {
    __shared__ float sW[64 * 64];
    int tid = threadIdx.x;
    for (int id = tid; id < 64 * 64; id += 256) sW[id] = v2W[id];
    __syncthreads();
    int b = tid;
    if (b >= NB) return;
    float v1[64];
#pragma unroll
    for (int j = 0; j < 64; j++) v1[j] = fmaxf(g_P[b * 80 + j] + v1b[j], 0.f);
    float adv[12];
#pragma unroll
    for (int j = 0; j < 12; j++) adv[j] = fmaxf(g_P[b * 80 + 64 + j] + advb[j], 0.f);
    float val = v3b[0];
    for (int i = 0; i < 64; i++) {
        float a0 = 0.f, a1 = 0.f, a2 = 0.f, a3 = 0.f;
#pragma unroll
        for (int j = 0; j < 64; j += 4) {
            a0 = fmaf(v1[j],     sW[(j)     * 64 + i], a0);
            a1 = fmaf(v1[j + 1], sW[(j + 1) * 64 + i], a1);
            a2 = fmaf(v1[j + 2], sW[(j + 2) * 64 + i], a2);
            a3 = fmaf(v1[j + 3], sW[(j + 3) * 64 + i], a3);
        }
        float a = (a0 + a1) + (a2 + a3) + v2b[i];
        val = fmaf(fmaxf(a, 0.f), v3W[i], val);
    }
#pragma unroll
    for (int h = 0; h < 3; h++) {
        float m = 0.25f * (adv[4 * h] + adv[4 * h + 1] + adv[4 * h + 2] + adv[4 * h + 3]);
#pragma unroll
        for (int a = 0; a < 4; a++)
            out[b * 12 + h * 4 + a] = val + adv[4 * h + a] - m;
    }
}

// ---------------- launch ----------------
extern "C" void kernel_launch(void* const* d_in, const int* in_sizes, int n_in,
                              void* d_out, int out_size) {
    const float* x    = (const float*)d_in[0];
    const void*  ei   = d_in[1];
    const float* ew   = (const float*)d_in[2];
    const float* W1   = (const float*)d_in[3];
    const float* b1   = (const float*)d_in[4];
    const float* W2   = (const float*)d_in[5];
    const float* b2   = (const float*)d_in[6];
    const float* advW = (const float*)d_in[7];
    const float* advb = (const float*)d_in[8];
    const float* v1W  = (const float*)d_in[9];
    const float* v1b  = (const float*)d_in[10];
    const float* v2W  = (const float*)d_in[11];
    const float* v2b  = (const float*)d_in[12];
    const float* v3W  = (const float*)d_in[13];
    const float* v3b  = (const float*)d_in[14];
    float* out = (float*)d_out;

    static int attr_done = 0;
    if (!attr_done) {
        cudaFuncSetAttribute(gcn2head_kernel, cudaFuncAttributeMaxDynamicSharedMemorySize, FG_SMEM);
        attr_done = 1;
    }

    zero_kernel<<<16, 256>>>((const int*)ei);
    degcnt_kernel<<<NEDGE / 256, 256>>>(ei, ew);
    scan_kernel<<<1, 1024>>>();
    fill_kernel<<<NEDGE / 256, 256>>>(ei, ew);
    agg16_kernel<<<NNODE, 512>>>(x);
    gemm1_kernel<<<NROWS / 8, 256>>>(W1, b1);
    agg128_kernel<<<NNODE, 512>>>();
    gcn2head_kernel<<<dim3(2, 1024), 256, FG_SMEM>>>(W2, b2, v1W, advW);
    reduceP_kernel<<<10, 256>>>();
    final_kernel<<<1, 256>>>(advb, v1b, v2W, v2b, v3W, v3b, out);
}